// round 8
// baseline (speedup 1.0000x reference)
#include <cuda_runtime.h>
#include <math.h>

#define IMAGE_W 256
#define IMAGE_H 256
#define EPS 1e-7f
#define SIGMA2 0.02f

#define B 16
#define N 64
#define C 3
#define PH 32
#define PW 32
#define TILE 32
#define PSZ (C*PH*PW)   // 3072 floats per stroke patch
#define NTILES (B * 64) // 1024
#define GRID 512        // each block handles exactly 2 tiles -> 1 balanced wave

// Grid-stride fused kernel: block processes tiles bt, bt+512.
// Per tile: warp 0 computes params + compacts survivors (1 barrier), then
// 512 threads gather (1 col x 2 rows x 3 ch each). Neighbor tap via shfl.
__global__ void __launch_bounds__(512) brush_kernel(
    const float* __restrict__ brushes,   // [B, N, 2]
    const float* __restrict__ patches,   // [B, N, 3, 32, 32]
    float* __restrict__ out)             // [B, 3, 256, 256]
{
    const int tid = threadIdx.x;
    const int lx  = tid & 31;
    const int g   = tid >> 5;            // 0..15

    __shared__ int4   cmeta[N];          // fx, fy, patch float-offset, pad
    __shared__ float4 cw[N];             // wx0, wx1, wy0/64, wy1/64
    __shared__ int    s_cnt;

    for (int bt = blockIdx.x; bt < NTILES; bt += GRID) {
        const int b    = bt >> 6;
        const int tile = bt & 63;
        const int tx0  = (tile & 7) * TILE;
        const int ty0  = (tile >> 3) * TILE;

        // ---- warp-0 prologue: params for 2 strokes/lane, ballot-compact ----
        if (tid < 32) {
            const int l = tid;
            const float2 br0 = ((const float2*)brushes)[b * N + l];
            const float2 br1 = ((const float2*)brushes)[b * N + l + 32];

            float mnx = fminf(br0.x, br1.x), mxx = fmaxf(br0.x, br1.x);
            float mny = fminf(br0.y, br1.y), mxy = fmaxf(br0.y, br1.y);
#pragma unroll
            for (int o = 16; o > 0; o >>= 1) {
                mnx = fminf(mnx, __shfl_xor_sync(0xffffffffu, mnx, o));
                mxx = fmaxf(mxx, __shfl_xor_sync(0xffffffffu, mxx, o));
                mny = fminf(mny, __shfl_xor_sync(0xffffffffu, mny, o));
                mxy = fmaxf(mxy, __shfl_xor_sync(0xffffffffu, mxy, o));
            }
            const float isx = 1.0f / (mxx - mnx + EPS) * (float)IMAGE_W;
            const float isy = 1.0f / (mxy - mny + EPS) * (float)IMAGE_H;

            int    fx[2], fy[2];
            float4 wt[2];
            bool   ov[2];
#pragma unroll
            for (int k = 0; k < 2; k++) {
                const float bx = k ? br1.x : br0.x;
                const float by = k ? br1.y : br0.y;
                const float axc = (bx - mnx) * isx - 15.5f;  // ux(q)=gx+q-15.5
                const float fx0f = floorf(axc);
                const float dx = axc - fx0f;
                const float ayc = (by - mny) * isy - 15.4f;  // uy(p)=gy+p-15.4
                const float fy0f = floorf(ayc);
                const float dy = ayc - fy0f;

                const float gx0 = __expf(-(dx * dx) / SIGMA2);
                const float gx1 = __expf(-((1.0f - dx) * (1.0f - dx)) / SIGMA2);
                const float wx0 = gx0 / (gx0 + gx1 + EPS);
                const float wx1 = gx1 / (gx0 + gx1 + EPS);

                const float gy0 = __expf(-(dy * dy) / SIGMA2);
                const float gy1 = __expf(-((1.0f - dy) * (1.0f - dy)) / SIGMA2);
                const float s  = 1.0f / 64.0f;               // fold /N into wy
                const float wy0 = gy0 / (gy0 + gy1 + EPS) * s;
                const float wy1 = gy1 / (gy0 + gy1 + EPS) * s;

                fx[k] = (int)fx0f;
                fy[k] = (int)fy0f;
                wt[k] = make_float4(wx0, wx1, wy0, wy1);
                ov[k] = !(fx[k] > tx0 + 31 || fx[k] + 32 < tx0 ||
                          fy[k] > ty0 + 31 || fy[k] + 32 < ty0);
            }

            const unsigned m0 = __ballot_sync(0xffffffffu, ov[0]);
            const unsigned m1 = __ballot_sync(0xffffffffu, ov[1]);
            const unsigned ltm = (1u << l) - 1u;
            const int base1 = __popc(m0);
            if (ov[0]) {
                const int pos = __popc(m0 & ltm);
                cmeta[pos] = make_int4(fx[0], fy[0], (b * N + l) * PSZ, 0);
                cw[pos]    = wt[0];
            }
            if (ov[1]) {
                const int pos = base1 + __popc(m1 & ltm);
                cmeta[pos] = make_int4(fx[1], fy[1], (b * N + l + 32) * PSZ, 0);
                cw[pos]    = wt[1];
            }
            if (l == 0) s_cnt = base1 + __popc(m1);
        }
        __syncthreads();
        const int cnt = s_cnt;

        // ---- gather ----
        const int x     = tx0 + lx;
        const int ybase = ty0 + g * 2;   // rows ybase, ybase+1

        float acc[C][2];
#pragma unroll
        for (int c = 0; c < C; c++) { acc[c][0] = 0.0f; acc[c][1] = 0.0f; }

#pragma unroll 2
        for (int s = 0; s < cnt; s++) {
            const int4   md = cmeta[s];
            const float4 wt = cw[s];
            const int i  = x - md.x;                   // window col (per lane)
            const int jb = ybase - md.y;               // window row (warp-uniform)
            if (jb < -1 || jb > 32) continue;          // warp-uniform skip
            const bool c0 = ((unsigned)i       < 32u);
            const bool c1 = ((unsigned)(i - 1) < 32u); // lane-0 boundary tap
            const float* Pn = patches + md.z + i;
#pragma unroll
            for (int c = 0; c < C; c++) {
                const float* Pc = Pn + c * (PH * PW);
                float h[3];
#pragma unroll
                for (int r = 0; r < 3; r++) {
                    const int rr = jb - 1 + r;
                    const bool rv = ((unsigned)rr < 32u);
                    const float p0 = (rv & c0) ? __ldg(Pc + rr * PW) : 0.0f;
                    // neighbor tap: lane lx's P[rr][i-1] == lane lx-1's p0
                    float p1 = __shfl_up_sync(0xffffffffu, p0, 1);
                    if (lx == 0)
                        p1 = (rv & c1) ? __ldg(Pc + rr * PW - 1) : 0.0f;
                    h[r] = wt.x * p0 + wt.y * p1;
                }
                acc[c][0] += wt.z * h[1] + wt.w * h[0];
                acc[c][1] += wt.z * h[2] + wt.w * h[1];
            }
        }

        // ---- coalesced stores: [b][c][y][x] ----
#pragma unroll
        for (int c = 0; c < C; c++) {
            float* oc = out + ((size_t)(b * C + c) * IMAGE_H) * IMAGE_W;
            oc[(size_t)(ybase    ) * IMAGE_W + x] = acc[c][0];
            oc[(size_t)(ybase + 1) * IMAGE_W + x] = acc[c][1];
        }
        __syncthreads();   // protect cmeta/cw before next tile's prologue
    }
}

extern "C" void kernel_launch(void* const* d_in, const int* in_sizes, int n_in,
                              void* d_out, int out_size)
{
    const float* brushes = (const float*)d_in[0];   // [16,64,2]
    const float* patches = (const float*)d_in[1];   // [16,64,3,32,32]
    float* out = (float*)d_out;                     // [16,3,256,256]

    brush_kernel<<<GRID, 512>>>(brushes, patches, out);
}

// round 9
// speedup vs baseline: 1.9698x; 1.9698x over previous
#include <cuda_runtime.h>
#include <math.h>

#define IMAGE_W 256
#define IMAGE_H 256
#define EPS 1e-7f
#define SIGMA2 0.02f

#define B 16
#define N 64
#define C 3
#define PH 32
#define PW 32
#define TILE 32
#define PSZ (C*PH*PW)   // 3072 floats per stroke patch
#define NTILES (B * 64) // 1024
#define GRID 512        // each block handles exactly 2 tiles -> 1 balanced wave

// Grid-stride fused kernel: block processes tiles bt and bt+512.
// Per tile: warp 0 computes params + compacts survivors (1 barrier), then
// 512 threads gather (1 col x 2 rows x 3 ch each), 18 independent LDGs/stroke.
__global__ void __launch_bounds__(512) brush_kernel(
    const float* __restrict__ brushes,   // [B, N, 2]
    const float* __restrict__ patches,   // [B, N, 3, 32, 32]
    float* __restrict__ out)             // [B, 3, 256, 256]
{
    const int tid = threadIdx.x;
    const int lx  = tid & 31;
    const int g   = tid >> 5;            // 0..15

    __shared__ int4   cmeta[N];          // fx, fy, patch float-offset, pad
    __shared__ float4 cw[N];             // wx0, wx1, wy0/64, wy1/64
    __shared__ int    s_cnt;

#pragma unroll
    for (int it = 0; it < 2; it++) {
        const int bt   = blockIdx.x + it * GRID;
        const int b    = bt >> 6;
        const int tile = bt & 63;
        const int tx0  = (tile & 7) * TILE;
        const int ty0  = (tile >> 3) * TILE;

        // ---- warp-0 prologue: params for 2 strokes/lane, ballot-compact ----
        if (tid < 32) {
            const int l = tid;
            const float2 br0 = ((const float2*)brushes)[b * N + l];
            const float2 br1 = ((const float2*)brushes)[b * N + l + 32];

            float mnx = fminf(br0.x, br1.x), mxx = fmaxf(br0.x, br1.x);
            float mny = fminf(br0.y, br1.y), mxy = fmaxf(br0.y, br1.y);
#pragma unroll
            for (int o = 16; o > 0; o >>= 1) {
                mnx = fminf(mnx, __shfl_xor_sync(0xffffffffu, mnx, o));
                mxx = fmaxf(mxx, __shfl_xor_sync(0xffffffffu, mxx, o));
                mny = fminf(mny, __shfl_xor_sync(0xffffffffu, mny, o));
                mxy = fmaxf(mxy, __shfl_xor_sync(0xffffffffu, mxy, o));
            }
            const float isx = 1.0f / (mxx - mnx + EPS) * (float)IMAGE_W;
            const float isy = 1.0f / (mxy - mny + EPS) * (float)IMAGE_H;

            int    fx[2], fy[2];
            float4 wt[2];
            bool   ov[2];
#pragma unroll
            for (int k = 0; k < 2; k++) {
                const float bx = k ? br1.x : br0.x;
                const float by = k ? br1.y : br0.y;
                const float axc = (bx - mnx) * isx - 15.5f;  // ux(q)=gx+q-15.5
                const float fx0f = floorf(axc);
                const float dx = axc - fx0f;
                const float ayc = (by - mny) * isy - 15.4f;  // uy(p)=gy+p-15.4
                const float fy0f = floorf(ayc);
                const float dy = ayc - fy0f;

                const float gx0 = __expf(-(dx * dx) / SIGMA2);
                const float gx1 = __expf(-((1.0f - dx) * (1.0f - dx)) / SIGMA2);
                const float wx0 = gx0 / (gx0 + gx1 + EPS);
                const float wx1 = gx1 / (gx0 + gx1 + EPS);

                const float gy0 = __expf(-(dy * dy) / SIGMA2);
                const float gy1 = __expf(-((1.0f - dy) * (1.0f - dy)) / SIGMA2);
                const float s  = 1.0f / 64.0f;               // fold /N into wy
                const float wy0 = gy0 / (gy0 + gy1 + EPS) * s;
                const float wy1 = gy1 / (gy0 + gy1 + EPS) * s;

                fx[k] = (int)fx0f;
                fy[k] = (int)fy0f;
                wt[k] = make_float4(wx0, wx1, wy0, wy1);
                ov[k] = !(fx[k] > tx0 + 31 || fx[k] + 32 < tx0 ||
                          fy[k] > ty0 + 31 || fy[k] + 32 < ty0);
            }

            const unsigned m0 = __ballot_sync(0xffffffffu, ov[0]);
            const unsigned m1 = __ballot_sync(0xffffffffu, ov[1]);
            const unsigned ltm = (1u << l) - 1u;
            const int base1 = __popc(m0);
            if (ov[0]) {
                const int pos = __popc(m0 & ltm);
                cmeta[pos] = make_int4(fx[0], fy[0], (b * N + l) * PSZ, 0);
                cw[pos]    = wt[0];
            }
            if (ov[1]) {
                const int pos = base1 + __popc(m1 & ltm);
                cmeta[pos] = make_int4(fx[1], fy[1], (b * N + l + 32) * PSZ, 0);
                cw[pos]    = wt[1];
            }
            if (l == 0) s_cnt = base1 + __popc(m1);
        }
        __syncthreads();
        const int cnt = s_cnt;

        // ---- gather (R7 body: 18 independent predicated LDGs per stroke) ----
        const int x     = tx0 + lx;
        const int ybase = ty0 + g * 2;   // rows ybase, ybase+1

        float acc[C][2];
#pragma unroll
        for (int c = 0; c < C; c++) { acc[c][0] = 0.0f; acc[c][1] = 0.0f; }

#pragma unroll 2
        for (int s = 0; s < cnt; s++) {
            const int4   md = cmeta[s];
            const float4 wt = cw[s];
            const int i  = x - md.x;                   // window col
            const int jb = ybase - md.y;               // window row of first output
            if (jb < -1 || jb > 32) continue;          // warp-uniform skip
            const bool c0 = ((unsigned)i       < 32u); // tap col i
            const bool c1 = ((unsigned)(i - 1) < 32u); // tap col i-1
            const float* Pn = patches + md.z + i;
#pragma unroll
            for (int c = 0; c < C; c++) {
                const float* Pc = Pn + c * (PH * PW);
                float h[3];
#pragma unroll
                for (int r = 0; r < 3; r++) {
                    const int rr = jb - 1 + r;
                    const bool rv = ((unsigned)rr < 32u);
                    const float p0 = (rv & c0) ? __ldg(Pc + rr * PW)     : 0.0f;
                    const float p1 = (rv & c1) ? __ldg(Pc + rr * PW - 1) : 0.0f;
                    h[r] = wt.x * p0 + wt.y * p1;
                }
                acc[c][0] += wt.z * h[1] + wt.w * h[0];
                acc[c][1] += wt.z * h[2] + wt.w * h[1];
            }
        }

        // ---- coalesced stores: [b][c][y][x] ----
#pragma unroll
        for (int c = 0; c < C; c++) {
            float* oc = out + ((size_t)(b * C + c) * IMAGE_H) * IMAGE_W;
            oc[(size_t)(ybase    ) * IMAGE_W + x] = acc[c][0];
            oc[(size_t)(ybase + 1) * IMAGE_W + x] = acc[c][1];
        }
        if (it == 0) __syncthreads();    // protect cmeta/cw for 2nd tile
    }
}

extern "C" void kernel_launch(void* const* d_in, const int* in_sizes, int n_in,
                              void* d_out, int out_size)
{
    const float* brushes = (const float*)d_in[0];   // [16,64,2]
    const float* patches = (const float*)d_in[1];   // [16,64,3,32,32]
    float* out = (float*)d_out;                     // [16,3,256,256]

    brush_kernel<<<GRID, 512>>>(brushes, patches, out);
}